// round 11
// baseline (speedup 1.0000x reference)
#include <cuda_runtime.h>
#include <cstdint>

#define FULL 0xffffffffu
typedef unsigned long long ull;

#define B_  8
#define L_  128
#define D_  512
#define H_  8
#define DV_ 64

// d_out layout: [final (B*L*D) | attn_value (B*H*L*L) | attn_relation (B*H*L*L)]
#define AV_OFF  (B_*L_*D_)             // 524288
#define AR_OFF  (AV_OFF + B_*H_*L_*L_) // 1572864

// ---------------- device scratch ----------------
__device__ __align__(16) float g_value[B_*H_*L_*DV_];      // (b,h,l,dv)
__device__ float g_esrc[B_*H_*L_];
__device__ float g_etgt[B_*H_*L_];
__device__ __align__(16) ull   g_wrp[256*8];               // Wr_eff pairs [kp][h]
__device__ __align__(16) float g_concat[B_*L_*2*D_];       // 4MB

// ---------------- helpers ----------------
__device__ __forceinline__ ull ffma2(ull a, ull b, ull c) {
    ull d;
    asm("fma.rn.f32x2 %0, %1, %2, %3;" : "=l"(d) : "l"(a), "l"(b), "l"(c));
    return d;
}
__device__ __forceinline__ float pairsum(ull v) {
    float2 f = *reinterpret_cast<float2*>(&v);
    return f.x + f.y;
}
__device__ __forceinline__ uint32_t saddr(const void* p) {
    return (uint32_t)__cvta_generic_to_shared(p);
}
__device__ __forceinline__ void cp8(uint32_t dst, const void* src) {
    asm volatile("cp.async.ca.shared.global [%0], [%1], 8;" :: "r"(dst), "l"(src));
}
__device__ __forceinline__ void cp16(uint32_t dst, const void* src) {
    asm volatile("cp.async.cg.shared.global [%0], [%1], 16;" :: "r"(dst), "l"(src));
}
__device__ __forceinline__ void cp_commit() {
    asm volatile("cp.async.commit_group;");
}
template<int N> __device__ __forceinline__ void cp_wait() {
    asm volatile("cp.async.wait_group %0;" :: "n"(N));
}

// ---------------- Wr_eff[k][h] ----------------
__global__ void k_wr(const float* __restrict__ Wrel, const float* __restrict__ wrel) {
    int gw = blockIdx.x * 8 + (threadIdx.x >> 5);
    int lane = threadIdx.x & 31;
    int k = gw >> 3, h = gw & 7;
    const float* r = Wrel + (size_t)k * 512 + h * 64;
    const float* w = wrel + h * 64;
    float s = r[lane] * w[lane] + r[lane + 32] * w[lane + 32];
    #pragma unroll
    for (int o = 16; o; o >>= 1) s += __shfl_xor_sync(FULL, s, o);
    if (lane == 0)
        ((float*)g_wrp)[(k >> 1) * 16 + h * 2 + (k & 1)] = s;
}

// ---------------- big fused kernel: block = (b,i), 256 threads (R9) ----------------
// R5 tiling (2 rows x 4 heads x ks2), W table resident in shared memory.
// dynamic smem: Asp 36864 + Wsp 16384 + red 4608 + scr 4224 = 62080B
__global__ __launch_bounds__(256, 3)
void k_big(const float* __restrict__ rel, const int* __restrict__ adj,
           const unsigned char* __restrict__ mask, float* __restrict__ out) {
    extern __shared__ __align__(16) unsigned char dsm[];
    typedef ull AspBuf[128][18];
    AspBuf* Asp = (AspBuf*)dsm;                          // [2] buffers 36864B
    ull* Wsp = (ull*)(dsm + 36864);                      // 2048 ull = 16384B
    float (*red)[9]   = (float(*)[9])(dsm + 53248);      // 4608B
    float (*scr)[132] = (float(*)[132])(dsm + 57856);    // 4224B

    int t = threadIdx.x;
    int bi = blockIdx.x, b = bi >> 7, i = bi & 127;
    const float* base = rel + (size_t)bi * 65536;

    int jt = t & 31, hg = (t >> 5) & 1, ks = (t >> 6) & 1, rs = t >> 7;
    int row0 = (rs << 6) + jt, row1 = row0 + 32;

    ull acc[2][4] = {};

    // stage W table (once) + window 0 in the same commit group
    #pragma unroll
    for (int q = 0; q < 4; q++) {
        int wi = (q << 8) + t;
        cp16(saddr(&Wsp[wi << 1]), g_wrp + (wi << 1));
    }
    #pragma unroll
    for (int q = 0; q < 4; q++) {
        int idx = (q << 8) + t, row = idx >> 3, sub = idx & 7;
        cp16(saddr(&Asp[0][row][sub << 1]), base + (size_t)row * 512 + (sub << 2));
    }
    cp_commit();

    for (int w = 0; w < 16; w++) {
        int buf = w & 1;
        if (w < 15) {
            #pragma unroll
            for (int q = 0; q < 4; q++) {
                int idx = (q << 8) + t, row = idx >> 3, sub = idx & 7;
                cp16(saddr(&Asp[buf ^ 1][row][sub << 1]),
                     base + (size_t)row * 512 + ((w + 1) << 5) + (sub << 2));
            }
            cp_commit();
            cp_wait<1>();
        } else {
            cp_wait<0>();
        }
        __syncthreads();
        const ull* wb = Wsp + (((w << 4) + (ks << 3)) << 3) + (hg << 2);
        #pragma unroll
        for (int p2 = 0; p2 < 4; p2++) {
            int pp = (ks << 3) + (p2 << 1);
            ulonglong2 a0 = *(const ulonglong2*)&Asp[buf][row0][pp];
            ulonglong2 a1 = *(const ulonglong2*)&Asp[buf][row1][pp];
            ulonglong2 wA0 = *(const ulonglong2*)(wb + ((p2 << 1)    ) * 8);
            ulonglong2 wA1 = *(const ulonglong2*)(wb + ((p2 << 1)    ) * 8 + 2);
            ulonglong2 wB0 = *(const ulonglong2*)(wb + ((p2 << 1) + 1) * 8);
            ulonglong2 wB1 = *(const ulonglong2*)(wb + ((p2 << 1) + 1) * 8 + 2);
            acc[0][0] = ffma2(a0.x, wA0.x, acc[0][0]);
            acc[0][1] = ffma2(a0.x, wA0.y, acc[0][1]);
            acc[0][2] = ffma2(a0.x, wA1.x, acc[0][2]);
            acc[0][3] = ffma2(a0.x, wA1.y, acc[0][3]);
            acc[1][0] = ffma2(a1.x, wA0.x, acc[1][0]);
            acc[1][1] = ffma2(a1.x, wA0.y, acc[1][1]);
            acc[1][2] = ffma2(a1.x, wA1.x, acc[1][2]);
            acc[1][3] = ffma2(a1.x, wA1.y, acc[1][3]);
            acc[0][0] = ffma2(a0.y, wB0.x, acc[0][0]);
            acc[0][1] = ffma2(a0.y, wB0.y, acc[0][1]);
            acc[0][2] = ffma2(a0.y, wB1.x, acc[0][2]);
            acc[0][3] = ffma2(a0.y, wB1.y, acc[0][3]);
            acc[1][0] = ffma2(a1.y, wB0.x, acc[1][0]);
            acc[1][1] = ffma2(a1.y, wB0.y, acc[1][1]);
            acc[1][2] = ffma2(a1.y, wB1.x, acc[1][2]);
            acc[1][3] = ffma2(a1.y, wB1.y, acc[1][3]);
        }
        __syncthreads();
    }

    int rid = jt + (hg << 5) + (rs << 6);
    if (ks == 1) {
        #pragma unroll
        for (int m = 0; m < 2; m++)
            #pragma unroll
            for (int n = 0; n < 4; n++)
                red[rid][(m << 2) + n] = pairsum(acc[m][n]);
    }
    __syncthreads();
    if (ks == 0) {
        #pragma unroll
        for (int m = 0; m < 2; m++) {
            int row = row0 + (m << 5);
            #pragma unroll
            for (int n = 0; n < 4; n++) {
                float x = pairsum(acc[m][n]) + red[rid][(m << 2) + n];
                x = x >= 0.f ? x : 0.2f * x;
                scr[(hg << 2) + n][row] = x;
            }
        }
    }
    __syncthreads();

    int h = t >> 5, lane = t & 31;
    const float* esrc = g_esrc + ((b << 3) + h) * 128;
    float et = g_etgt[((b << 3) + h) * 128 + i];
    const int* adjrow = adj + ((size_t)(((b << 3) + h) * 128 + i) << 7);
    float xv[4], xr[4];
    bool bad[4];
    #pragma unroll
    for (int m = 0; m < 4; m++) {
        int j = lane + (m << 5);
        bool bd = (mask[(bi << 7) + j] != 0) || (adjrow[j] == 0);
        bad[m] = bd;
        float ev = et + esrc[j];
        ev = ev >= 0.f ? ev : 0.2f * ev;
        xv[m] = bd ? -1e12f : ev;
        xr[m] = bd ? -1e12f : scr[h][j];
    }

    auto softmax_store = [&](float x0, float x1, float x2, float x3, size_t ob) {
        float mx = fmaxf(fmaxf(x0, x1), fmaxf(x2, x3));
        #pragma unroll
        for (int o = 16; o; o >>= 1) mx = fmaxf(mx, __shfl_xor_sync(FULL, mx, o));
        float e0 = expf(x0 - mx), e1 = expf(x1 - mx);
        float e2 = expf(x2 - mx), e3 = expf(x3 - mx);
        float Z = e0 + e1 + e2 + e3;
        #pragma unroll
        for (int o = 16; o; o >>= 1) Z += __shfl_xor_sync(FULL, Z, o);
        float inv = 1.0f / Z;
        float p0 = e0 * inv, p1 = e1 * inv, p2 = e2 * inv, p3 = e3 * inv;
        float s = p0 + p1 + p2 + p3;
        #pragma unroll
        for (int o = 16; o; o >>= 1) s += __shfl_xor_sync(FULL, s, o);
        float rinv = 1.0f / fmaxf(s, 1e-12f);
        p0 *= rinv; p1 *= rinv; p2 *= rinv; p3 *= rinv;
        if (bad[0]) p0 = 0.f;
        if (bad[1]) p1 = 0.f;
        if (bad[2]) p2 = 0.f;
        if (bad[3]) p3 = 0.f;
        out[ob + lane +  0] = p0; out[ob + lane + 32] = p1;
        out[ob + lane + 64] = p2; out[ob + lane + 96] = p3;
    };
    size_t rb = (size_t)(((b << 3) + h) * 128 + i) * 128;
    softmax_store(xv[0], xv[1], xv[2], xv[3], (size_t)AV_OFF + rb);
    softmax_store(xr[0], xr[1], xr[2], xr[3], (size_t)AR_OFF + rb);
}

// ---------------- unified pipelined 64x64 GEMM (R9, [9]-pad) ----------------
// EPI=1: value GEMM -> g_value + fused e_src/e_tgt
// EPI=3: out_v/out_r -> g_concat
template<int EPI>
__global__ __launch_bounds__(256, 2)
void k_gemm(const float* __restrict__ A, const float* __restrict__ Bm,
            float* __restrict__ C, int K,
            const float* __restrict__ bias, const float* __restrict__ resid,
            const float* __restrict__ wsrc, const float* __restrict__ wtgt) {
    __shared__ ull Ap[2][64][9];
    __shared__ ull Bp[2][64][9];
    __shared__ float ered[2][64][17];

    int t = threadIdx.x;
    int tx = t & 15, ty = t >> 4;

    const float* Aptr; const float* Bptr;
    int lda, ldb, row0 = 0, col0 = 0;
    int s3 = 0, bh3 = 0, ihalf3 = 0;
    if (EPI == 3) {
        int bx = blockIdx.x;
        s3 = bx & 1; ihalf3 = (bx >> 1) & 1; bh3 = bx >> 2;
        Aptr = C + (s3 ? AR_OFF : AV_OFF) + (size_t)bh3 * 16384 + (size_t)ihalf3 * 64 * 128;
        Bptr = g_value + (size_t)bh3 * 8192;
        lda = 128; ldb = 64;
    } else {
        col0 = blockIdx.x << 6; row0 = blockIdx.y << 6;
        Aptr = A + (size_t)row0 * 512;
        Bptr = Bm + col0;
        lda = 512; ldb = 512;
    }

    ull acc[4][4];
    #pragma unroll
    for (int m = 0; m < 4; m++)
        #pragma unroll
        for (int n = 0; n < 4; n++) acc[m][n] = 0ull;

    int W = K >> 4;
    int bk = t >> 4, bn0 = (t & 15) << 2;

    float4 vB = *(const float4*)(Bptr + (size_t)bk * ldb + bn0);
    #pragma unroll
    for (int q = 0; q < 2; q++) {
        int fi = (q << 8) + t, row = fi >> 3, pc = fi & 7;
        cp8(saddr(&Ap[0][row][pc]), Aptr + (size_t)row * lda + (pc << 1));
    }
    cp_commit();

    for (int w = 0; w < W; w++) {
        int buf = w & 1;
        ((float*)&Bp[buf][bn0 + 0][bk >> 1])[bk & 1] = vB.x;
        ((float*)&Bp[buf][bn0 + 1][bk >> 1])[bk & 1] = vB.y;
        ((float*)&Bp[buf][bn0 + 2][bk >> 1])[bk & 1] = vB.z;
        ((float*)&Bp[buf][bn0 + 3][bk >> 1])[bk & 1] = vB.w;
        if (w < W - 1) {
            vB = *(const float4*)(Bptr + (size_t)(((w + 1) << 4) + bk) * ldb + bn0);
            #pragma unroll
            for (int q = 0; q < 2; q++) {
                int fi = (q << 8) + t, row = fi >> 3, pc = fi & 7;
                cp8(saddr(&Ap[buf ^ 1][row][pc]),
                    Aptr + (size_t)row * lda + ((w + 1) << 4) + (pc << 1));
            }
            cp_commit();
            cp_wait<1>();
        } else {
            cp_wait<0>();
        }
        __syncthreads();
        #pragma unroll
        for (int p = 0; p < 8; p++) {
            ull a2[4], b2[4];
            #pragma unroll
            for (int m = 0; m < 4; m++) a2[m] = Ap[buf][ty + (m << 4)][p];
            #pragma unroll
            for (int n = 0; n < 4; n++) b2[n] = Bp[buf][tx + (n << 4)][p];
            #pragma unroll
            for (int m = 0; m < 4; m++)
                #pragma unroll
                for (int n = 0; n < 4; n++)
                    acc[m][n] = ffma2(a2[m], b2[n], acc[m][n]);
        }
        __syncthreads();
    }

    float v[4][4];
    #pragma unroll
    for (int m = 0; m < 4; m++)
        #pragma unroll
        for (int n = 0; n < 4; n++) v[m][n] = pairsum(acc[m][n]);

    if (EPI == 1) {
        int h = col0 >> 6;
        float ps[4] = {0,0,0,0}, pt[4] = {0,0,0,0};
        #pragma unroll
        for (int n = 0; n < 4; n++) {
            int dv = tx + (n << 4);
            float ws = wsrc[h * 64 + dv], wt = wtgt[h * 64 + dv];
            #pragma unroll
            for (int m = 0; m < 4; m++) {
                int rg = row0 + ty + (m << 4);
                int b = rg >> 7, l = rg & 127;
                g_value[(size_t)((((b << 3) | h) << 7) | l) * 64 + dv] = v[m][n];
                ps[m] += v[m][n] * ws;
                pt[m] += v[m][n] * wt;
            }
        }
        #pragma unroll
        for (int m = 0; m < 4; m++) {
            ered[0][ty + (m << 4)][tx] = ps[m];
            ered[1][ty + (m << 4)][tx] = pt[m];
        }
        __syncthreads();
        if (t < 128) {
            int row = t & 63, sel = t >> 6;
            float s = 0.f;
            #pragma unroll
            for (int x = 0; x < 16; x++) s += ered[sel][row][x];
            int rg = row0 + row, b = rg >> 7, l = rg & 127;
            (sel ? g_etgt : g_esrc)[((b << 3) + h) * 128 + l] = s;
        }
    } else {
        int b = bh3 >> 3, h = bh3 & 7;
        #pragma unroll
        for (int m = 0; m < 4; m++) {
            int ig = (ihalf3 << 6) + ty + (m << 4);
            #pragma unroll
            for (int n = 0; n < 4; n++) {
                int dv = tx + (n << 4);
                g_concat[(size_t)(b * 128 + ig) * 1024 + s3 * 512 + h * 64 + dv] = v[m][n];
            }
        }
    }
}

// ---------------- final GEMM: M32 x N64 x K1024 + bias + residual ----------------
// grid (8,32) = 256 blocks, 3 blocks/SM target
__global__ __launch_bounds__(256, 3)
void k_final(const float* __restrict__ Wf, const float* __restrict__ bias,
             const float* __restrict__ resid, float* __restrict__ out) {
    __shared__ ull Ap[2][32][9];
    __shared__ ull Bp[2][64][9];
    int t = threadIdx.x;
    int tx = t & 15, ty = t >> 4;
    int col0 = blockIdx.x << 6, row0 = blockIdx.y << 5;
    const float* Aptr = g_concat + (size_t)row0 * 1024;
    const float* Bptr = Wf + col0;
    int bk = t >> 4, bn0 = (t & 15) << 2;
    int arow = t >> 3, apc = t & 7;

    ull acc[2][4];
    #pragma unroll
    for (int m = 0; m < 2; m++)
        #pragma unroll
        for (int n = 0; n < 4; n++) acc[m][n] = 0ull;

    float4 vB = *(const float4*)(Bptr + (size_t)bk * 512 + bn0);
    cp8(saddr(&Ap[0][arow][apc]), Aptr + (size_t)arow * 1024 + (apc << 1));
    cp_commit();

    for (int w = 0; w < 64; w++) {
        int buf = w & 1;
        ((float*)&Bp[buf][bn0 + 0][bk >> 1])[bk & 1] = vB.x;
        ((float*)&Bp[buf][bn0 + 1][bk >> 1])[bk & 1] = vB.y;
        ((float*)&Bp[buf][bn0 + 2][bk >> 1])[bk & 1] = vB.z;
        ((float*)&Bp[buf][bn0 + 3][bk >> 1])[bk & 1] = vB.w;
        if (w < 63) {
            vB = *(const float4*)(Bptr + (size_t)(((w + 1) << 4) + bk) * 512 + bn0);
            cp8(saddr(&Ap[buf ^ 1][arow][apc]),
                Aptr + (size_t)arow * 1024 + ((w + 1) << 4) + (apc << 1));
            cp_commit();
            cp_wait<1>();
        } else {
            cp_wait<0>();
        }
        __syncthreads();
        #pragma unroll
        for (int p = 0; p < 8; p++) {
            ull a2[2], b2[4];
            #pragma unroll
            for (int m = 0; m < 2; m++) a2[m] = Ap[buf][ty + (m << 4)][p];
            #pragma unroll
            for (int n = 0; n < 4; n++) b2[n] = Bp[buf][tx + (n << 4)][p];
            #pragma unroll
            for (int m = 0; m < 2; m++)
                #pragma unroll
                for (int n = 0; n < 4; n++)
                    acc[m][n] = ffma2(a2[m], b2[n], acc[m][n]);
        }
        __syncthreads();
    }

    #pragma unroll
    for (int m = 0; m < 2; m++) {
        int rg = row0 + ty + (m << 4);
        #pragma unroll
        for (int n = 0; n < 4; n++) {
            int col = col0 + tx + (n << 4);
            out[(size_t)rg * 512 + col] =
                pairsum(acc[m][n]) + bias[col] + resid[(size_t)rg * 512 + col];
        }
    }
}

// ---------------- launch ----------------
extern "C" void kernel_launch(void* const* d_in, const int* in_sizes, int n_in,
                              void* d_out, int out_size) {
    const float* inp     = (const float*)d_in[0];
    const float* relin   = (const float*)d_in[1];
    const unsigned char* mask = (const unsigned char*)d_in[2];
    const int*   adj     = (const int*)d_in[3];
    const float* W_value = (const float*)d_in[7];
    const float* W_rel   = (const float*)d_in[8];
    const float* w_src   = (const float*)d_in[9];
    const float* w_tgt   = (const float*)d_in[10];
    const float* w_rel   = (const float*)d_in[11];
    const float* W_final = (const float*)d_in[12];
    const float* b_final = (const float*)d_in[13];
    float* out = (float*)d_out;

    static int smem_set = 0;
    if (!smem_set) {
        cudaFuncSetAttribute(k_big, cudaFuncAttributeMaxDynamicSharedMemorySize, 62080);
        smem_set = 1;
    }

    k_wr<<<512, 256>>>(W_rel, w_rel);
    k_gemm<1><<<dim3(8, 16), 256>>>(inp, W_value, nullptr, 512,
                                    nullptr, nullptr, w_src, w_tgt);
    k_big<<<1024, 256, 62080>>>(relin, adj, mask, out);
    k_gemm<3><<<256, 256>>>(nullptr, nullptr, out, 128,
                            nullptr, nullptr, nullptr, nullptr);
    k_final<<<dim3(8, 32), 256>>>(W_final, b_final, inp, out);
}

// round 12
// speedup vs baseline: 1.1787x; 1.1787x over previous
#include <cuda_runtime.h>
#include <cstdint>

#define FULL 0xffffffffu
typedef unsigned long long ull;

#define B_  8
#define L_  128
#define D_  512
#define H_  8
#define DV_ 64

// d_out layout: [final (B*L*D) | attn_value (B*H*L*L) | attn_relation (B*H*L*L)]
#define AV_OFF  (B_*L_*D_)             // 524288
#define AR_OFF  (AV_OFF + B_*H_*L_*L_) // 1572864

// ---------------- device scratch ----------------
__device__ __align__(16) float g_value[B_*H_*L_*DV_];      // (b,h,l,dv)
__device__ float g_esrc[B_*H_*L_];
__device__ float g_etgt[B_*H_*L_];
__device__ __align__(16) ull   g_wrp[256*8];               // Wr_eff pairs [kp][h]
__device__ __align__(16) float g_concat[B_*L_*2*D_];       // 4MB

// ---------------- helpers ----------------
__device__ __forceinline__ ull ffma2(ull a, ull b, ull c) {
    ull d;
    asm("fma.rn.f32x2 %0, %1, %2, %3;" : "=l"(d) : "l"(a), "l"(b), "l"(c));
    return d;
}
__device__ __forceinline__ float pairsum(ull v) {
    float2 f = *reinterpret_cast<float2*>(&v);
    return f.x + f.y;
}
__device__ __forceinline__ uint32_t saddr(const void* p) {
    return (uint32_t)__cvta_generic_to_shared(p);
}
__device__ __forceinline__ void cp16(uint32_t dst, const void* src) {
    asm volatile("cp.async.cg.shared.global [%0], [%1], 16;" :: "r"(dst), "l"(src));
}
__device__ __forceinline__ void cp_commit() {
    asm volatile("cp.async.commit_group;");
}
template<int N> __device__ __forceinline__ void cp_wait() {
    asm volatile("cp.async.wait_group %0;" :: "n"(N));
}

// ---------------- Wr_eff[k][h] ----------------
__global__ void k_wr(const float* __restrict__ Wrel, const float* __restrict__ wrel) {
    int gw = blockIdx.x * 8 + (threadIdx.x >> 5);
    int lane = threadIdx.x & 31;
    int k = gw >> 3, h = gw & 7;
    const float* r = Wrel + (size_t)k * 512 + h * 64;
    const float* w = wrel + h * 64;
    float s = r[lane] * w[lane] + r[lane + 32] * w[lane + 32];
    #pragma unroll
    for (int o = 16; o; o >>= 1) s += __shfl_xor_sync(FULL, s, o);
    if (lane == 0)
        ((float*)g_wrp)[(k >> 1) * 16 + h * 2 + (k & 1)] = s;
}

// ---------------- big fused kernel: block = (b,i), 256 threads (R9) ----------------
__global__ __launch_bounds__(256, 3)
void k_big(const float* __restrict__ rel, const int* __restrict__ adj,
           const unsigned char* __restrict__ mask, float* __restrict__ out) {
    extern __shared__ __align__(16) unsigned char dsm[];
    typedef ull AspBuf[128][18];
    AspBuf* Asp = (AspBuf*)dsm;                          // [2] buffers 36864B
    ull* Wsp = (ull*)(dsm + 36864);                      // 2048 ull = 16384B
    float (*red)[9]   = (float(*)[9])(dsm + 53248);      // 4608B
    float (*scr)[132] = (float(*)[132])(dsm + 57856);    // 4224B

    int t = threadIdx.x;
    int bi = blockIdx.x, b = bi >> 7, i = bi & 127;
    const float* base = rel + (size_t)bi * 65536;

    int jt = t & 31, hg = (t >> 5) & 1, ks = (t >> 6) & 1, rs = t >> 7;
    int row0 = (rs << 6) + jt, row1 = row0 + 32;

    ull acc[2][4] = {};

    #pragma unroll
    for (int q = 0; q < 4; q++) {
        int wi = (q << 8) + t;
        cp16(saddr(&Wsp[wi << 1]), g_wrp + (wi << 1));
    }
    #pragma unroll
    for (int q = 0; q < 4; q++) {
        int idx = (q << 8) + t, row = idx >> 3, sub = idx & 7;
        cp16(saddr(&Asp[0][row][sub << 1]), base + (size_t)row * 512 + (sub << 2));
    }
    cp_commit();

    for (int w = 0; w < 16; w++) {
        int buf = w & 1;
        if (w < 15) {
            #pragma unroll
            for (int q = 0; q < 4; q++) {
                int idx = (q << 8) + t, row = idx >> 3, sub = idx & 7;
                cp16(saddr(&Asp[buf ^ 1][row][sub << 1]),
                     base + (size_t)row * 512 + ((w + 1) << 5) + (sub << 2));
            }
            cp_commit();
            cp_wait<1>();
        } else {
            cp_wait<0>();
        }
        __syncthreads();
        const ull* wb = Wsp + (((w << 4) + (ks << 3)) << 3) + (hg << 2);
        #pragma unroll
        for (int p2 = 0; p2 < 4; p2++) {
            int pp = (ks << 3) + (p2 << 1);
            ulonglong2 a0 = *(const ulonglong2*)&Asp[buf][row0][pp];
            ulonglong2 a1 = *(const ulonglong2*)&Asp[buf][row1][pp];
            ulonglong2 wA0 = *(const ulonglong2*)(wb + ((p2 << 1)    ) * 8);
            ulonglong2 wA1 = *(const ulonglong2*)(wb + ((p2 << 1)    ) * 8 + 2);
            ulonglong2 wB0 = *(const ulonglong2*)(wb + ((p2 << 1) + 1) * 8);
            ulonglong2 wB1 = *(const ulonglong2*)(wb + ((p2 << 1) + 1) * 8 + 2);
            acc[0][0] = ffma2(a0.x, wA0.x, acc[0][0]);
            acc[0][1] = ffma2(a0.x, wA0.y, acc[0][1]);
            acc[0][2] = ffma2(a0.x, wA1.x, acc[0][2]);
            acc[0][3] = ffma2(a0.x, wA1.y, acc[0][3]);
            acc[1][0] = ffma2(a1.x, wA0.x, acc[1][0]);
            acc[1][1] = ffma2(a1.x, wA0.y, acc[1][1]);
            acc[1][2] = ffma2(a1.x, wA1.x, acc[1][2]);
            acc[1][3] = ffma2(a1.x, wA1.y, acc[1][3]);
            acc[0][0] = ffma2(a0.y, wB0.x, acc[0][0]);
            acc[0][1] = ffma2(a0.y, wB0.y, acc[0][1]);
            acc[0][2] = ffma2(a0.y, wB1.x, acc[0][2]);
            acc[0][3] = ffma2(a0.y, wB1.y, acc[0][3]);
            acc[1][0] = ffma2(a1.y, wB0.x, acc[1][0]);
            acc[1][1] = ffma2(a1.y, wB0.y, acc[1][1]);
            acc[1][2] = ffma2(a1.y, wB1.x, acc[1][2]);
            acc[1][3] = ffma2(a1.y, wB1.y, acc[1][3]);
        }
        __syncthreads();
    }

    int rid = jt + (hg << 5) + (rs << 6);
    if (ks == 1) {
        #pragma unroll
        for (int m = 0; m < 2; m++)
            #pragma unroll
            for (int n = 0; n < 4; n++)
                red[rid][(m << 2) + n] = pairsum(acc[m][n]);
    }
    __syncthreads();
    if (ks == 0) {
        #pragma unroll
        for (int m = 0; m < 2; m++) {
            int row = row0 + (m << 5);
            #pragma unroll
            for (int n = 0; n < 4; n++) {
                float x = pairsum(acc[m][n]) + red[rid][(m << 2) + n];
                x = x >= 0.f ? x : 0.2f * x;
                scr[(hg << 2) + n][row] = x;
            }
        }
    }
    __syncthreads();

    int h = t >> 5, lane = t & 31;
    const float* esrc = g_esrc + ((b << 3) + h) * 128;
    float et = g_etgt[((b << 3) + h) * 128 + i];
    const int* adjrow = adj + ((size_t)(((b << 3) + h) * 128 + i) << 7);
    float xv[4], xr[4];
    bool bad[4];
    #pragma unroll
    for (int m = 0; m < 4; m++) {
        int j = lane + (m << 5);
        bool bd = (mask[(bi << 7) + j] != 0) || (adjrow[j] == 0);
        bad[m] = bd;
        float ev = et + esrc[j];
        ev = ev >= 0.f ? ev : 0.2f * ev;
        xv[m] = bd ? -1e12f : ev;
        xr[m] = bd ? -1e12f : scr[h][j];
    }

    auto softmax_store = [&](float x0, float x1, float x2, float x3, size_t ob) {
        float mx = fmaxf(fmaxf(x0, x1), fmaxf(x2, x3));
        #pragma unroll
        for (int o = 16; o; o >>= 1) mx = fmaxf(mx, __shfl_xor_sync(FULL, mx, o));
        float e0 = expf(x0 - mx), e1 = expf(x1 - mx);
        float e2 = expf(x2 - mx), e3 = expf(x3 - mx);
        float Z = e0 + e1 + e2 + e3;
        #pragma unroll
        for (int o = 16; o; o >>= 1) Z += __shfl_xor_sync(FULL, Z, o);
        float inv = 1.0f / Z;
        float p0 = e0 * inv, p1 = e1 * inv, p2 = e2 * inv, p3 = e3 * inv;
        float s = p0 + p1 + p2 + p3;
        #pragma unroll
        for (int o = 16; o; o >>= 1) s += __shfl_xor_sync(FULL, s, o);
        float rinv = 1.0f / fmaxf(s, 1e-12f);
        p0 *= rinv; p1 *= rinv; p2 *= rinv; p3 *= rinv;
        if (bad[0]) p0 = 0.f;
        if (bad[1]) p1 = 0.f;
        if (bad[2]) p2 = 0.f;
        if (bad[3]) p3 = 0.f;
        out[ob + lane +  0] = p0; out[ob + lane + 32] = p1;
        out[ob + lane + 64] = p2; out[ob + lane + 96] = p3;
    };
    size_t rb = (size_t)(((b << 3) + h) * 128 + i) * 128;
    softmax_store(xv[0], xv[1], xv[2], xv[3], (size_t)AV_OFF + rb);
    softmax_store(xr[0], xr[1], xr[2], xr[3], (size_t)AR_OFF + rb);
}

// ---------------- unified pipelined 64x64 GEMM, 32-k windows ----------------
// A: Ap[2][64][18] ull (stride 144B: cp16-aligned, LDS.128 conflict-free)
// B: Bp[2][64][17] ull (stride 136B: LDS.64 conflict-free, 4-way STS as before)
// EPI=1: value GEMM -> g_value + fused e_src/e_tgt
// EPI=2: final GEMM -> out + bias + resid
// EPI=3: out_v/out_r -> g_concat
template<int EPI>
__global__ __launch_bounds__(256, 2)
void k_gemm(const float* __restrict__ A, const float* __restrict__ Bm,
            float* __restrict__ C, int K,
            const float* __restrict__ bias, const float* __restrict__ resid,
            const float* __restrict__ wsrc, const float* __restrict__ wtgt) {
    __shared__ __align__(16) ull Ap[2][64][18];
    __shared__ ull Bp[2][64][17];
    __shared__ float ered[2][64][17];

    int t = threadIdx.x;
    int tx = t & 15, ty = t >> 4;

    const float* Aptr; const float* Bptr;
    int lda, ldb, row0 = 0, col0 = 0;
    int s3 = 0, bh3 = 0, ihalf3 = 0;
    if (EPI == 3) {
        int bx = blockIdx.x;
        s3 = bx & 1; ihalf3 = (bx >> 1) & 1; bh3 = bx >> 2;
        Aptr = C + (s3 ? AR_OFF : AV_OFF) + (size_t)bh3 * 16384 + (size_t)ihalf3 * 64 * 128;
        Bptr = g_value + (size_t)bh3 * 8192;
        lda = 128; ldb = 64;
    } else {
        col0 = blockIdx.x << 6; row0 = blockIdx.y << 6;
        Aptr = (EPI == 2) ? g_concat : A;
        Bptr = Bm;
        lda = (EPI == 2) ? 1024 : 512;
        ldb = 512;
        Aptr += (size_t)row0 * lda;
        Bptr += col0;
    }

    ull acc[4][4];
    #pragma unroll
    for (int m = 0; m < 4; m++)
        #pragma unroll
        for (int n = 0; n < 4; n++) acc[m][n] = 0ull;

    int W = K >> 5;                           // 32-k windows
    int bk = t >> 4, bn0 = (t & 15) << 2;     // B stage: k rows bk, bk+16

    float4 vB0 = *(const float4*)(Bptr + (size_t)bk * ldb + bn0);
    float4 vB1 = *(const float4*)(Bptr + (size_t)(bk + 16) * ldb + bn0);
    #pragma unroll
    for (int q = 0; q < 2; q++) {
        int fi = (q << 8) + t, row = fi >> 3, sub = fi & 7;
        cp16(saddr(&Ap[0][row][sub << 1]), Aptr + (size_t)row * lda + (sub << 2));
    }
    cp_commit();

    for (int w = 0; w < W; w++) {
        int buf = w & 1;
        // store B(w) transposed: pair index k>>1, half k&1
        {
            int p0 = bk >> 1, h0 = bk & 1;
            ((float*)&Bp[buf][bn0 + 0][p0])[h0] = vB0.x;
            ((float*)&Bp[buf][bn0 + 1][p0])[h0] = vB0.y;
            ((float*)&Bp[buf][bn0 + 2][p0])[h0] = vB0.z;
            ((float*)&Bp[buf][bn0 + 3][p0])[h0] = vB0.w;
            int p1 = p0 + 8;
            ((float*)&Bp[buf][bn0 + 0][p1])[h0] = vB1.x;
            ((float*)&Bp[buf][bn0 + 1][p1])[h0] = vB1.y;
            ((float*)&Bp[buf][bn0 + 2][p1])[h0] = vB1.z;
            ((float*)&Bp[buf][bn0 + 3][p1])[h0] = vB1.w;
        }
        if (w < W - 1) {
            vB0 = *(const float4*)(Bptr + (size_t)(((w + 1) << 5) + bk) * ldb + bn0);
            vB1 = *(const float4*)(Bptr + (size_t)(((w + 1) << 5) + bk + 16) * ldb + bn0);
            #pragma unroll
            for (int q = 0; q < 2; q++) {
                int fi = (q << 8) + t, row = fi >> 3, sub = fi & 7;
                cp16(saddr(&Ap[buf ^ 1][row][sub << 1]),
                     Aptr + (size_t)row * lda + ((w + 1) << 5) + (sub << 2));
            }
            cp_commit();
            cp_wait<1>();
        } else {
            cp_wait<0>();
        }
        __syncthreads();
        #pragma unroll
        for (int p2 = 0; p2 < 8; p2++) {
            ulonglong2 a2[4];
            ull bl[4], bh[4];
            #pragma unroll
            for (int m = 0; m < 4; m++)
                a2[m] = *(const ulonglong2*)&Ap[buf][ty + (m << 4)][p2 << 1];
            #pragma unroll
            for (int n = 0; n < 4; n++) {
                bl[n] = Bp[buf][tx + (n << 4)][(p2 << 1)];
                bh[n] = Bp[buf][tx + (n << 4)][(p2 << 1) + 1];
            }
            #pragma unroll
            for (int m = 0; m < 4; m++)
                #pragma unroll
                for (int n = 0; n < 4; n++) {
                    acc[m][n] = ffma2(a2[m].x, bl[n], acc[m][n]);
                    acc[m][n] = ffma2(a2[m].y, bh[n], acc[m][n]);
                }
        }
        __syncthreads();
    }

    float v[4][4];
    #pragma unroll
    for (int m = 0; m < 4; m++)
        #pragma unroll
        for (int n = 0; n < 4; n++) v[m][n] = pairsum(acc[m][n]);

    if (EPI == 1) {
        int h = col0 >> 6;
        float ps[4] = {0,0,0,0}, pt[4] = {0,0,0,0};
        #pragma unroll
        for (int n = 0; n < 4; n++) {
            int dv = tx + (n << 4);
            float ws = wsrc[h * 64 + dv], wt = wtgt[h * 64 + dv];
            #pragma unroll
            for (int m = 0; m < 4; m++) {
                int rg = row0 + ty + (m << 4);
                int b = rg >> 7, l = rg & 127;
                g_value[(size_t)((((b << 3) | h) << 7) | l) * 64 + dv] = v[m][n];
                ps[m] += v[m][n] * ws;
                pt[m] += v[m][n] * wt;
            }
        }
        #pragma unroll
        for (int m = 0; m < 4; m++) {
            ered[0][ty + (m << 4)][tx] = ps[m];
            ered[1][ty + (m << 4)][tx] = pt[m];
        }
        __syncthreads();
        if (t < 128) {
            int row = t & 63, sel = t >> 6;
            float s = 0.f;
            #pragma unroll
            for (int x = 0; x < 16; x++) s += ered[sel][row][x];
            int rg = row0 + row, b = rg >> 7, l = rg & 127;
            (sel ? g_etgt : g_esrc)[((b << 3) + h) * 128 + l] = s;
        }
    } else if (EPI == 2) {
        #pragma unroll
        for (int m = 0; m < 4; m++) {
            int rg = row0 + ty + (m << 4);
            #pragma unroll
            for (int n = 0; n < 4; n++) {
                int col = col0 + tx + (n << 4);
                C[(size_t)rg * 512 + col] = v[m][n] + bias[col] + resid[(size_t)rg * 512 + col];
            }
        }
    } else {
        int b = bh3 >> 3, h = bh3 & 7;
        #pragma unroll
        for (int m = 0; m < 4; m++) {
            int ig = (ihalf3 << 6) + ty + (m << 4);
            #pragma unroll
            for (int n = 0; n < 4; n++) {
                int dv = tx + (n << 4);
                g_concat[(size_t)(b * 128 + ig) * 1024 + s3 * 512 + h * 64 + dv] = v[m][n];
            }
        }
    }
}

// ---------------- launch ----------------
extern "C" void kernel_launch(void* const* d_in, const int* in_sizes, int n_in,
                              void* d_out, int out_size) {
    const float* inp     = (const float*)d_in[0];
    const float* relin   = (const float*)d_in[1];
    const unsigned char* mask = (const unsigned char*)d_in[2];
    const int*   adj     = (const int*)d_in[3];
    const float* W_value = (const float*)d_in[7];
    const float* W_rel   = (const float*)d_in[8];
    const float* w_src   = (const float*)d_in[9];
    const float* w_tgt   = (const float*)d_in[10];
    const float* w_rel   = (const float*)d_in[11];
    const float* W_final = (const float*)d_in[12];
    const float* b_final = (const float*)d_in[13];
    float* out = (float*)d_out;

    static int smem_set = 0;
    if (!smem_set) {
        cudaFuncSetAttribute(k_big, cudaFuncAttributeMaxDynamicSharedMemorySize, 62080);
        smem_set = 1;
    }

    k_wr<<<512, 256>>>(W_rel, w_rel);
    k_gemm<1><<<dim3(8, 16), 256>>>(inp, W_value, nullptr, 512,
                                    nullptr, nullptr, w_src, w_tgt);
    k_big<<<1024, 256, 62080>>>(relin, adj, mask, out);
    k_gemm<3><<<256, 256>>>(nullptr, nullptr, out, 128,
                            nullptr, nullptr, nullptr, nullptr);
    k_gemm<2><<<dim3(8, 16), 256>>>(nullptr, W_final, out, 1024,
                                    b_final, inp, nullptr, nullptr);
}